// round 3
// baseline (speedup 1.0000x reference)
#include <cuda_runtime.h>
#include <math.h>

#define BSZ 4
#define TSEQ 2048
#define CDIM 1024
#define HN 16
#define DH 64

// scratch (allocation-free rule: __device__ globals, referenced directly by symbol)
__device__ float g_q[(size_t)BSZ * HN * TSEQ * DH];    // (B,H,T,D)
__device__ float g_att[(size_t)BSZ * TSEQ * CDIM];     // (B,T,C)

// ---------------------------------------------------------------------------
// GEMM: out = A(8192,1024) @ W(1024,1024) + bias
// OUT_MODE 0: out[m*1024 + n]               (row-major B*T x C), out = param
// OUT_MODE 1: out[((b*16+h)*2048+t)*64+d]   (B,H,T,D), out = param
// OUT_MODE 2: same layout as 1 but writes to g_q (no pointer param needed)
// IN_MODE  0: A = param
// IN_MODE  1: A = g_att
// ---------------------------------------------------------------------------
template <int IN_MODE, int OUT_MODE>
__global__ __launch_bounds__(256) void gemm_k(const float* __restrict__ Ap,
                                              const float* __restrict__ W,
                                              const float* __restrict__ bias,
                                              float* __restrict__ outp) {
    const float* A = (IN_MODE == 0) ? Ap : (const float*)g_att;
    float* out = (OUT_MODE == 2) ? (float*)g_q : outp;

    __shared__ float As[8][128];   // transposed A tile: As[k][m]
    __shared__ float Bs[8][128];   // Bs[k][n]

    const int tid = threadIdx.x;
    const int tx = tid & 15;       // col group
    const int ty = tid >> 4;       // row group
    const int m0 = blockIdx.y * 128;
    const int n0 = blockIdx.x * 128;

    const int arow = tid >> 1;           // 0..127
    const int akq  = (tid & 1) * 4;      // 0 or 4
    const int brow = tid >> 5;           // 0..7
    const int bcol = (tid & 31) * 4;     // 0..124

    const float* Aptr = A + (size_t)(m0 + arow) * 1024 + akq;
    const float* Wptr = W + (size_t)brow * 1024 + n0 + bcol;

    float acc[8][8];
#pragma unroll
    for (int i = 0; i < 8; i++)
#pragma unroll
        for (int j = 0; j < 8; j++) acc[i][j] = 0.0f;

    for (int kt = 0; kt < 1024; kt += 8) {
        float4 a4 = *(const float4*)(Aptr + kt);
        float4 b4 = *(const float4*)(Wptr + (size_t)kt * 1024);
        __syncthreads();   // previous compute done reading smem
        As[akq + 0][arow] = a4.x;
        As[akq + 1][arow] = a4.y;
        As[akq + 2][arow] = a4.z;
        As[akq + 3][arow] = a4.w;
        *(float4*)&Bs[brow][bcol] = b4;
        __syncthreads();
#pragma unroll
        for (int kk = 0; kk < 8; kk++) {
            float4 a0 = *(float4*)&As[kk][ty * 8];
            float4 a1 = *(float4*)&As[kk][ty * 8 + 4];
            float4 b0 = *(float4*)&Bs[kk][tx * 8];
            float4 b1 = *(float4*)&Bs[kk][tx * 8 + 4];
            float av[8] = {a0.x, a0.y, a0.z, a0.w, a1.x, a1.y, a1.z, a1.w};
            float bv[8] = {b0.x, b0.y, b0.z, b0.w, b1.x, b1.y, b1.z, b1.w};
#pragma unroll
            for (int i = 0; i < 8; i++)
#pragma unroll
                for (int j = 0; j < 8; j++) acc[i][j] += av[i] * bv[j];
        }
    }

    // epilogue
    const int nf = n0 + tx * 8;                // first of 8 consecutive n
    float4 bia0 = *(const float4*)(bias + nf);
    float4 bia1 = *(const float4*)(bias + nf + 4);
    float bb[8] = {bia0.x, bia0.y, bia0.z, bia0.w, bia1.x, bia1.y, bia1.z, bia1.w};

#pragma unroll
    for (int i = 0; i < 8; i++) {
        const int m = m0 + ty * 8 + i;
        float4 r0 = make_float4(acc[i][0] + bb[0], acc[i][1] + bb[1],
                                acc[i][2] + bb[2], acc[i][3] + bb[3]);
        float4 r1 = make_float4(acc[i][4] + bb[4], acc[i][5] + bb[5],
                                acc[i][6] + bb[6], acc[i][7] + bb[7]);
        if (OUT_MODE == 0) {
            float* p = out + (size_t)m * 1024 + nf;
            *(float4*)p = r0;
            *(float4*)(p + 4) = r1;
        } else {
            const int b = m >> 11, t = m & 2047;
            const int h = nf >> 6, d0 = nf & 63;   // 8 cols stay in one head
            float* p = out + (((size_t)(b * 16 + h) * 2048 + t) * 64 + d0);
            *(float4*)p = r0;
            *(float4*)(p + 4) = r1;
        }
    }
}

// ---------------------------------------------------------------------------
// Causal flash attention, fp32. Q from g_q, output to g_att.
// Grid: (T/64, B*H). Block: 256 threads (16 tx x 16 ty).
// 64q x 64k tiles; thread owns 4x4 of S and 4x4 of O (rows ri=ty*4, cols cj=tx*4).
// Smem: Qt[dim][row], KP (Kt[dim][key] -> reused as Ps[row][key]), Vs[key][dim].
// ---------------------------------------------------------------------------
__global__ __launch_bounds__(256) void attn_k(const float* __restrict__ k,
                                              const float* __restrict__ v) {
    const float* q = (const float*)g_q;
    float* yo = (float*)g_att;

    __shared__ float Qt[64][64];
    __shared__ float KP[64][64];
    __shared__ float Vs[64][64];

    const int tid = threadIdx.x;
    const int tx = tid & 15;
    const int ty = tid >> 4;
    const int ri = ty * 4;
    const int cj = tx * 4;
    const int bh = blockIdx.y;        // b*16 + h
    const int t0 = blockIdx.x * 64;

    const float* qb = q + (size_t)bh * TSEQ * DH;
    const float* kb = k + (size_t)bh * TSEQ * DH;
    const float* vb = v + (size_t)bh * TSEQ * DH;

    // load Q tile transposed + fold 1/sqrt(D)
#pragma unroll
    for (int it = 0; it < 4; it++) {
        int idx = tid + it * 256;      // 0..1023
        int r = idx >> 4;
        int c4 = (idx & 15) * 4;
        float4 a = *(const float4*)(qb + (size_t)(t0 + r) * 64 + c4);
        Qt[c4 + 0][r] = a.x * 0.125f;
        Qt[c4 + 1][r] = a.y * 0.125f;
        Qt[c4 + 2][r] = a.z * 0.125f;
        Qt[c4 + 3][r] = a.w * 0.125f;
    }

    float o[4][4];
    float mi[4], li[4];
#pragma unroll
    for (int i = 0; i < 4; i++) {
        mi[i] = -1e30f;
        li[i] = 0.0f;
#pragma unroll
        for (int j = 0; j < 4; j++) o[i][j] = 0.0f;
    }

    const int ntiles = blockIdx.x + 1;
    for (int jt = 0; jt < ntiles; jt++) {
        const int j0 = jt * 64;
        __syncthreads();   // prior iteration done reading KP(P) and Vs
        // K transposed + V natural
#pragma unroll
        for (int it = 0; it < 4; it++) {
            int idx = tid + it * 256;
            int r = idx >> 4;
            int c4 = (idx & 15) * 4;
            float4 a = *(const float4*)(kb + (size_t)(j0 + r) * 64 + c4);
            KP[c4 + 0][r] = a.x;
            KP[c4 + 1][r] = a.y;
            KP[c4 + 2][r] = a.z;
            KP[c4 + 3][r] = a.w;
            float4 bvv = *(const float4*)(vb + (size_t)(j0 + r) * 64 + c4);
            *(float4*)&Vs[r][c4] = bvv;
        }
        __syncthreads();

        // S = Q K^T
        float s[4][4];
#pragma unroll
        for (int i = 0; i < 4; i++)
#pragma unroll
            for (int j = 0; j < 4; j++) s[i][j] = 0.0f;
#pragma unroll
        for (int kk = 0; kk < 64; kk++) {
            float4 aq = *(float4*)&Qt[kk][ri];
            float4 bk = *(float4*)&KP[kk][cj];
            float av[4] = {aq.x, aq.y, aq.z, aq.w};
            float bw[4] = {bk.x, bk.y, bk.z, bk.w};
#pragma unroll
            for (int i = 0; i < 4; i++)
#pragma unroll
                for (int j = 0; j < 4; j++) s[i][j] += av[i] * bw[j];
        }

        // causal mask (only diagonal tile can violate)
        if (jt == blockIdx.x) {
#pragma unroll
            for (int i = 0; i < 4; i++)
#pragma unroll
                for (int j = 0; j < 4; j++)
                    if (cj + j > ri + i) s[i][j] = -1e30f;
        }

        // row max across the 16 tx threads (consecutive lanes within warp)
        float tm[4];
#pragma unroll
        for (int i = 0; i < 4; i++) {
            tm[i] = fmaxf(fmaxf(s[i][0], s[i][1]), fmaxf(s[i][2], s[i][3]));
        }
#pragma unroll
        for (int off = 1; off < 16; off <<= 1) {
#pragma unroll
            for (int i = 0; i < 4; i++)
                tm[i] = fmaxf(tm[i], __shfl_xor_sync(0xffffffffu, tm[i], off));
        }

        float p[4][4], rs[4];
#pragma unroll
        for (int i = 0; i < 4; i++) {
            float mnew = fmaxf(mi[i], tm[i]);
            float alpha = __expf(mi[i] - mnew);
            mi[i] = mnew;
            float lsum = 0.0f;
#pragma unroll
            for (int j = 0; j < 4; j++) {
                p[i][j] = __expf(s[i][j] - mnew);
                lsum += p[i][j];
            }
            rs[i] = lsum;
            li[i] *= alpha;
#pragma unroll
            for (int j = 0; j < 4; j++) o[i][j] *= alpha;
        }
#pragma unroll
        for (int off = 1; off < 16; off <<= 1) {
#pragma unroll
            for (int i = 0; i < 4; i++)
                rs[i] += __shfl_xor_sync(0xffffffffu, rs[i], off);
        }
#pragma unroll
        for (int i = 0; i < 4; i++) li[i] += rs[i];

        __syncthreads();   // all threads done reading KP as K^T
        // store P into KP as Ps[row][key]
#pragma unroll
        for (int i = 0; i < 4; i++)
            *(float4*)&KP[ri + i][cj] = make_float4(p[i][0], p[i][1], p[i][2], p[i][3]);
        __syncwarp();      // row's P producers/consumers share a warp

        // O += P V
#pragma unroll
        for (int kk = 0; kk < 64; kk++) {
            float a0 = KP[ri + 0][kk];
            float a1 = KP[ri + 1][kk];
            float a2 = KP[ri + 2][kk];
            float a3 = KP[ri + 3][kk];
            float4 bv4 = *(float4*)&Vs[kk][cj];
            float bw[4] = {bv4.x, bv4.y, bv4.z, bv4.w};
#pragma unroll
            for (int j = 0; j < 4; j++) {
                o[0][j] += a0 * bw[j];
                o[1][j] += a1 * bw[j];
                o[2][j] += a2 * bw[j];
                o[3][j] += a3 * bw[j];
            }
        }
    }

    // normalize + write to (B,T,C) scratch
    const int b = bh >> 4;
    const int h = bh & 15;
#pragma unroll
    for (int i = 0; i < 4; i++) {
        float inv = 1.0f / li[i];
        int tq = t0 + ri + i;
        float* p = yo + ((size_t)(b * 2048 + tq) * 1024 + h * 64 + cj);
        *(float4*)p = make_float4(o[i][0] * inv, o[i][1] * inv,
                                  o[i][2] * inv, o[i][3] * inv);
    }
}

// ---------------------------------------------------------------------------
extern "C" void kernel_launch(void* const* d_in, const int* in_sizes, int n_in,
                              void* d_out, int out_size) {
    const float* x  = (const float*)d_in[0];
    const float* wq = (const float*)d_in[1];
    const float* bq = (const float*)d_in[2];
    const float* wk = (const float*)d_in[3];
    const float* bk = (const float*)d_in[4];
    const float* wv = (const float*)d_in[5];
    const float* bv = (const float*)d_in[6];
    const float* wp = (const float*)d_in[7];
    const float* bp = (const float*)d_in[8];

    float* out  = (float*)d_out;
    float* kout = out + (size_t)BSZ * TSEQ * CDIM;                 // present[0] (k)
    float* vout = kout + (size_t)BSZ * HN * TSEQ * DH;             // present[1] (v)

    dim3 gg(8, 64);   // N/128, M/128

    // q -> g_q (OUT_MODE 2, symbol-direct), k/v -> present region of d_out
    gemm_k<0, 2><<<gg, 256>>>(x, wq, bq, nullptr);
    gemm_k<0, 1><<<gg, 256>>>(x, wk, bk, kout);
    gemm_k<0, 1><<<gg, 256>>>(x, wv, bv, vout);

    // attention: g_q x kout/vout -> g_att
    attn_k<<<dim3(TSEQ / 64, BSZ * HN), 256>>>(kout, vout);

    // projection: g_att @ wp + bp -> y region of d_out
    gemm_k<1, 0><<<gg, 256>>>(nullptr, wp, bp, out);
}

// round 5
// speedup vs baseline: 1.4902x; 1.4902x over previous
#include <cuda_runtime.h>
#include <stdint.h>
#include <math.h>

#define BSZ 4
#define TSEQ 2048
#define CDIM 1024
#define HN 16
#define DH 64

// __device__ scratch (allocation-free rule)
__device__ float g_q[(size_t)BSZ * HN * TSEQ * DH];    // (B,H,T,D)
__device__ float g_att[(size_t)BSZ * TSEQ * CDIM];     // (B,T,C)
__device__ float g_wt[4][(size_t)CDIM * CDIM];         // transposed+rounded weights [n][k]

__device__ __forceinline__ float to_tf32(float x) {
    float r; asm("cvt.rna.tf32.f32 %0, %1;" : "=f"(r) : "f"(x)); return r;
}

__device__ __forceinline__ void mma_tf32(float* d, const float* a, const float* b) {
    asm("mma.sync.aligned.m16n8k8.row.col.f32.tf32.tf32.f32 "
        "{%0,%1,%2,%3}, {%4,%5,%6,%7}, {%8,%9}, {%0,%1,%2,%3};"
        : "+f"(d[0]), "+f"(d[1]), "+f"(d[2]), "+f"(d[3])
        : "f"(a[0]), "f"(a[1]), "f"(a[2]), "f"(a[3]), "f"(b[0]), "f"(b[1]));
}

// ---------------------------------------------------------------------------
// weight transpose + tf32 rounding: g_wt[z][n][k] = rna(w_z[k][n])
// ---------------------------------------------------------------------------
__global__ void transpose_w(const float* __restrict__ w0, const float* __restrict__ w1,
                            const float* __restrict__ w2, const float* __restrict__ w3) {
    __shared__ float t[32][33];
    const float* src = (blockIdx.z == 0) ? w0 : (blockIdx.z == 1) ? w1
                     : (blockIdx.z == 2) ? w2 : w3;
    float* dst = g_wt[blockIdx.z];
    const int n0 = blockIdx.x * 32, k0 = blockIdx.y * 32;
    const int x = threadIdx.x, y = threadIdx.y;
#pragma unroll
    for (int i = 0; i < 32; i += 8)
        t[y + i][x] = src[(size_t)(k0 + y + i) * CDIM + n0 + x];
    __syncthreads();
#pragma unroll
    for (int i = 0; i < 32; i += 8)
        dst[(size_t)(n0 + y + i) * CDIM + k0 + x] = to_tf32(t[x][y + i]);
}

// ---------------------------------------------------------------------------
// tf32 mma.sync GEMM: out(8192x1024) = A @ W + bias
// Block 128x128, BK=32, 256 threads (8 warps, 2x4 warp grid, warp = 64x32).
// Smem K-layout permuted within each 8-group: src col k -> pos (k%4)*2 + k/4,
// so every mma fragment load is one LDS.64.
// IN_MODE  0: A = Ap        1: A = g_att
// OUT_MODE 0: row-major out 1: (B,H,T,D) out   2: (B,H,T,D) into g_q
// ---------------------------------------------------------------------------
template <int IN_MODE, int OUT_MODE>
__global__ __launch_bounds__(256, 2)
void gemm_tc(const float* __restrict__ Ap, const float* __restrict__ bias,
             float* __restrict__ outp, int wsel) {
    const float* A = (IN_MODE == 0) ? Ap : (const float*)g_att;
    const float* Wt = g_wt[wsel];
    float* out = (OUT_MODE == 2) ? (float*)g_q : outp;

    __shared__ float smA[128][36];
    __shared__ float smB[128][36];
    __shared__ float smBias[128];

    const int tid = threadIdx.x;
    const int lane = tid & 31;
    const int wid = tid >> 5;
    const int warp_m = wid >> 2;     // 0..1  (64 rows)
    const int warp_n = wid & 3;      // 0..3  (32 cols)
    const int g = lane >> 2;         // 0..7
    const int c = lane & 3;          // 0..3
    const int m0 = blockIdx.y * 128;
    const int n0 = blockIdx.x * 128;

    if (tid < 128) smBias[tid] = bias[n0 + tid];

    // gmem load coords: each thread 4 float4 from A and 4 from B per ktile
    const int r_ld = tid >> 1;            // two threads per row? no: idx pattern below
    (void)r_ld;

    float acc[4][4][4];
#pragma unroll
    for (int mt = 0; mt < 4; mt++)
#pragma unroll
        for (int nt = 0; nt < 4; nt++)
#pragma unroll
            for (int i = 0; i < 4; i++) acc[mt][nt][i] = 0.0f;

    for (int kt = 0; kt < 32; kt++) {
        // prefetch gmem -> regs
        float4 aq[4], bq[4];
#pragma unroll
        for (int it = 0; it < 4; it++) {
            int idx = tid + it * 256;        // 0..1023
            int r = idx >> 3;                // 0..127
            int k4 = (idx & 7) * 4;          // 0,4,...,28
            aq[it] = *(const float4*)(A + (size_t)(m0 + r) * CDIM + kt * 32 + k4);
            bq[it] = *(const float4*)(Wt + (size_t)(n0 + r) * CDIM + kt * 32 + k4);
        }
        __syncthreads();   // previous compute done reading smem
#pragma unroll
        for (int it = 0; it < 4; it++) {
            int idx = tid + it * 256;
            int r = idx >> 3;
            int k4 = (idx & 7) * 4;
            int base = (k4 & ~7) + ((k4 & 4) ? 1 : 0);   // group8*8 + phase
            float av[4] = {aq[it].x, aq[it].y, aq[it].z, aq[it].w};
            float bv[4] = {bq[it].x, bq[it].y, bq[it].z, bq[it].w};
#pragma unroll
            for (int i = 0; i < 4; i++) {
                smA[r][base + i * 2] = to_tf32(av[i]);
                smB[r][base + i * 2] = bv[i];            // W pre-rounded
            }
        }
        __syncthreads();

#pragma unroll
        for (int ks = 0; ks < 4; ks++) {
            float afr[4][4];
#pragma unroll
            for (int mt = 0; mt < 4; mt++) {
                int r0 = warp_m * 64 + mt * 16 + g;
                float2 A0 = *(float2*)&smA[r0][ks * 8 + 2 * c];
                float2 A1 = *(float2*)&smA[r0 + 8][ks * 8 + 2 * c];
                afr[mt][0] = A0.x; afr[mt][1] = A1.x;
                afr[mt][2] = A0.y; afr[mt][3] = A1.y;
            }
            float bfr[4][2];
#pragma unroll
            for (int nt = 0; nt < 4; nt++) {
                int n = warp_n * 32 + nt * 8 + g;
                float2 B0 = *(float2*)&smB[n][ks * 8 + 2 * c];
                bfr[nt][0] = B0.x; bfr[nt][1] = B0.y;
            }
#pragma unroll
            for (int mt = 0; mt < 4; mt++)
#pragma unroll
                for (int nt = 0; nt < 4; nt++)
                    mma_tf32(acc[mt][nt], afr[mt], bfr[nt]);
        }
    }

    // epilogue: c0/c1 at (row0, 2c/2c+1), c2/c3 at (row0+8, ...)
#pragma unroll
    for (int mt = 0; mt < 4; mt++) {
        const int row0 = m0 + warp_m * 64 + mt * 16 + g;
#pragma unroll
        for (int nt = 0; nt < 4; nt++) {
            const int cl = warp_n * 32 + nt * 8 + 2 * c;   // local col
            const int nb = n0 + cl;
            float2 v0 = make_float2(acc[mt][nt][0] + smBias[cl],
                                    acc[mt][nt][1] + smBias[cl + 1]);
            float2 v1 = make_float2(acc[mt][nt][2] + smBias[cl],
                                    acc[mt][nt][3] + smBias[cl + 1]);
            if (OUT_MODE == 0) {
                *(float2*)(out + (size_t)row0 * CDIM + nb) = v0;
                *(float2*)(out + (size_t)(row0 + 8) * CDIM + nb) = v1;
            } else {
                const int h = nb >> 6, d0 = nb & 63;
                const int b0 = row0 >> 11, t0 = row0 & 2047;
                const int b1 = (row0 + 8) >> 11, t1 = (row0 + 8) & 2047;
                *(float2*)(out + (((size_t)(b0 * HN + h) * TSEQ + t0) * DH + d0)) = v0;
                *(float2*)(out + (((size_t)(b1 * HN + h) * TSEQ + t1) * DH + d0)) = v1;
            }
        }
    }
}

// ---------------------------------------------------------------------------
// Causal flash attention, fp32 (unchanged, known good). Q from g_q -> g_att.
// ---------------------------------------------------------------------------
__global__ __launch_bounds__(256) void attn_k(const float* __restrict__ k,
                                              const float* __restrict__ v) {
    const float* q = (const float*)g_q;
    float* yo = (float*)g_att;

    __shared__ float Qt[64][64];
    __shared__ float KP[64][64];
    __shared__ float Vs[64][64];

    const int tid = threadIdx.x;
    const int tx = tid & 15;
    const int ty = tid >> 4;
    const int ri = ty * 4;
    const int cj = tx * 4;
    const int bh = blockIdx.y;
    const int t0 = blockIdx.x * 64;

    const float* qb = q + (size_t)bh * TSEQ * DH;
    const float* kb = k + (size_t)bh * TSEQ * DH;
    const float* vb = v + (size_t)bh * TSEQ * DH;

#pragma unroll
    for (int it = 0; it < 4; it++) {
        int idx = tid + it * 256;
        int r = idx >> 4;
        int c4 = (idx & 15) * 4;
        float4 a = *(const float4*)(qb + (size_t)(t0 + r) * 64 + c4);
        Qt[c4 + 0][r] = a.x * 0.125f;
        Qt[c4 + 1][r] = a.y * 0.125f;
        Qt[c4 + 2][r] = a.z * 0.125f;
        Qt[c4 + 3][r] = a.w * 0.125f;
    }

    float o[4][4];
    float mi[4], li[4];
#pragma unroll
    for (int i = 0; i < 4; i++) {
        mi[i] = -1e30f;
        li[i] = 0.0f;
#pragma unroll
        for (int j = 0; j < 4; j++) o[i][j] = 0.0f;
    }

    const int ntiles = blockIdx.x + 1;
    for (int jt = 0; jt < ntiles; jt++) {
        const int j0 = jt * 64;
        __syncthreads();
#pragma unroll
        for (int it = 0; it < 4; it++) {
            int idx = tid + it * 256;
            int r = idx >> 4;
            int c4 = (idx & 15) * 4;
            float4 a = *(const float4*)(kb + (size_t)(j0 + r) * 64 + c4);
            KP[c4 + 0][r] = a.x;
            KP[c4 + 1][r] = a.y;
            KP[c4 + 2][r] = a.z;
            KP[c4 + 3][r] = a.w;
            float4 bvv = *(const float4*)(vb + (size_t)(j0 + r) * 64 + c4);
            *(float4*)&Vs[r][c4] = bvv;
        }
        __syncthreads();

        float s[4][4];
#pragma unroll
        for (int i = 0; i < 4; i++)
#pragma unroll
            for (int j = 0; j < 4; j++) s[i][j] = 0.0f;
#pragma unroll
        for (int kk = 0; kk < 64; kk++) {
            float4 aq = *(float4*)&Qt[kk][ri];
            float4 bk = *(float4*)&KP[kk][cj];
            float av[4] = {aq.x, aq.y, aq.z, aq.w};
            float bw[4] = {bk.x, bk.y, bk.z, bk.w};
#pragma unroll
            for (int i = 0; i < 4; i++)
#pragma unroll
                for (int j = 0; j < 4; j++) s[i][j] += av[i] * bw[j];
        }

        if (jt == blockIdx.x) {
#pragma unroll
            for (int i = 0; i < 4; i++)
#pragma unroll
                for (int j = 0; j < 4; j++)
                    if (cj + j > ri + i) s[i][j] = -1e30f;
        }

        float tm[4];
#pragma unroll
        for (int i = 0; i < 4; i++)
            tm[i] = fmaxf(fmaxf(s[i][0], s[i][1]), fmaxf(s[i][2], s[i][3]));
#pragma unroll
        for (int off = 1; off < 16; off <<= 1) {
#pragma unroll
            for (int i = 0; i < 4; i++)
                tm[i] = fmaxf(tm[i], __shfl_xor_sync(0xffffffffu, tm[i], off));
        }

        float p[4][4], rs[4];
#pragma unroll
        for (int i = 0; i < 4; i++) {
            float mnew = fmaxf(mi[i], tm[i]);
            float alpha = __expf(mi[i] - mnew);
            mi[i] = mnew;
            float lsum = 0.0f;
#pragma unroll
            for (int j = 0; j < 4; j++) {
                p[i][j] = __expf(s[i][j] - mnew);
                lsum += p[i][j];
            }
            rs[i] = lsum;
            li[i] *= alpha;
#pragma unroll
            for (int j = 0; j < 4; j++) o[i][j] *= alpha;
        }
#pragma unroll
        for (int off = 1; off < 16; off <<= 1) {
#pragma unroll
            for (int i = 0; i < 4; i++)
                rs[i] += __shfl_xor_sync(0xffffffffu, rs[i], off);
        }
#pragma unroll
        for (int i = 0; i < 4; i++) li[i] += rs[i];

        __syncthreads();
#pragma unroll
        for (int i = 0; i < 4; i++)
            *(float4*)&KP[ri + i][cj] = make_float4(p[i][0], p[i][1], p[i][2], p[i][3]);
        __syncwarp();

#pragma unroll
        for (int kk = 0; kk < 64; kk++) {
            float a0 = KP[ri + 0][kk];
            float a1 = KP[ri + 1][kk];
            float a2 = KP[ri + 2][kk];
            float a3 = KP[ri + 3][kk];
            float4 bv4 = *(float4*)&Vs[kk][cj];
            float bw[4] = {bv4.x, bv4.y, bv4.z, bv4.w};
#pragma unroll
            for (int j = 0; j < 4; j++) {
                o[0][j] += a0 * bw[j];
                o[1][j] += a1 * bw[j];
                o[2][j] += a2 * bw[j];
                o[3][j] += a3 * bw[j];
            }
        }
    }

    const int b = bh >> 4;
    const int h = bh & 15;
#pragma unroll
    for (int i = 0; i < 4; i++) {
        float inv = 1.0f / li[i];
        int tq = t0 + ri + i;
        float* p = yo + ((size_t)(b * 2048 + tq) * 1024 + h * 64 + cj);
        *(float4*)p = make_float4(o[i][0] * inv, o[i][1] * inv,
                                  o[i][2] * inv, o[i][3] * inv);
    }
}

// ---------------------------------------------------------------------------
extern "C" void kernel_launch(void* const* d_in, const int* in_sizes, int n_in,
                              void* d_out, int out_size) {
    const float* x  = (const float*)d_in[0];
    const float* wq = (const float*)d_in[1];
    const float* bq = (const float*)d_in[2];
    const float* wk = (const float*)d_in[3];
    const float* bk = (const float*)d_in[4];
    const float* wv = (const float*)d_in[5];
    const float* bv = (const float*)d_in[6];
    const float* wp = (const float*)d_in[7];
    const float* bp = (const float*)d_in[8];

    float* out  = (float*)d_out;
    float* kout = out + (size_t)BSZ * TSEQ * CDIM;       // present[0] (k)
    float* vout = kout + (size_t)BSZ * HN * TSEQ * DH;   // present[1] (v)

    transpose_w<<<dim3(32, 32, 4), dim3(32, 8)>>>(wq, wk, wv, wp);

    dim3 gg(8, 64);   // N/128, M/128
    gemm_tc<0, 2><<<gg, 256>>>(x, bq, nullptr, 0);   // q -> g_q
    gemm_tc<0, 1><<<gg, 256>>>(x, bk, kout, 1);      // k -> present[0]
    gemm_tc<0, 1><<<gg, 256>>>(x, bv, vout, 2);      // v -> present[1]

    attn_k<<<dim3(TSEQ / 64, BSZ * HN), 256>>>(kout, vout);

    gemm_tc<1, 0><<<gg, 256>>>(nullptr, bp, out, 3); // y = att @ wp + bp
}

// round 7
// speedup vs baseline: 2.4584x; 1.6497x over previous
#include <cuda_runtime.h>
#include <stdint.h>
#include <math.h>

#define BSZ 4
#define TSEQ 2048
#define CDIM 1024
#define HN 16
#define DH 64

// __device__ scratch (allocation-free rule)
__device__ float g_q[(size_t)BSZ * HN * TSEQ * DH];    // (B,H,T,D)
__device__ float g_att[(size_t)BSZ * TSEQ * CDIM];     // (B,T,C)
__device__ float g_wt[4][(size_t)CDIM * CDIM];         // transposed+rounded weights [n][k]
__device__ float g_vt[(size_t)BSZ * HN * DH * TSEQ];   // V transposed (B,H,D,T), tf32-rounded

__device__ __forceinline__ float to_tf32(float x) {
    float r; asm("cvt.rna.tf32.f32 %0, %1;" : "=f"(r) : "f"(x)); return r;
}

__device__ __forceinline__ void mma_tf32(float* d, const float* a, const float* b) {
    asm("mma.sync.aligned.m16n8k8.row.col.f32.tf32.tf32.f32 "
        "{%0,%1,%2,%3}, {%4,%5,%6,%7}, {%8,%9}, {%0,%1,%2,%3};"
        : "+f"(d[0]), "+f"(d[1]), "+f"(d[2]), "+f"(d[3])
        : "f"(a[0]), "f"(a[1]), "f"(a[2]), "f"(a[3]), "f"(b[0]), "f"(b[1]));
}

// ---------------------------------------------------------------------------
// weight transpose + tf32 rounding: g_wt[z][n][k] = rna(w_z[k][n])
// ---------------------------------------------------------------------------
__global__ void transpose_w(const float* __restrict__ w0, const float* __restrict__ w1,
                            const float* __restrict__ w2, const float* __restrict__ w3) {
    __shared__ float t[32][33];
    const float* src = (blockIdx.z == 0) ? w0 : (blockIdx.z == 1) ? w1
                     : (blockIdx.z == 2) ? w2 : w3;
    float* dst = g_wt[blockIdx.z];
    const int n0 = blockIdx.x * 32, k0 = blockIdx.y * 32;
    const int x = threadIdx.x, y = threadIdx.y;
#pragma unroll
    for (int i = 0; i < 32; i += 8)
        t[y + i][x] = src[(size_t)(k0 + y + i) * CDIM + n0 + x];
    __syncthreads();
#pragma unroll
    for (int i = 0; i < 32; i += 8)
        dst[(size_t)(n0 + y + i) * CDIM + k0 + x] = to_tf32(t[x][y + i]);
}

// ---------------------------------------------------------------------------
// V transpose + tf32 rounding: g_vt[bh][d][t] = rna(vout[bh][t][d])
// ---------------------------------------------------------------------------
__global__ void transpose_v(const float* __restrict__ v) {
    __shared__ float t[32][33];
    const int bh = blockIdx.z;
    const int t0 = blockIdx.x * 32, d0 = blockIdx.y * 32;
    const int x = threadIdx.x, y = threadIdx.y;
    const float* src = v + (size_t)bh * TSEQ * DH;
    float* dst = (float*)g_vt + (size_t)bh * DH * TSEQ;
#pragma unroll
    for (int i = 0; i < 32; i += 8)
        t[y + i][x] = src[(size_t)(t0 + y + i) * DH + d0 + x];
    __syncthreads();
#pragma unroll
    for (int i = 0; i < 32; i += 8)
        dst[(size_t)(d0 + y + i) * TSEQ + t0 + x] = to_tf32(t[x][y + i]);
}

// ---------------------------------------------------------------------------
// tf32 mma.sync GEMM (unchanged, verified): out = A @ W + bias
// ---------------------------------------------------------------------------
template <int IN_MODE, int OUT_MODE>
__global__ __launch_bounds__(256, 2)
void gemm_tc(const float* __restrict__ Ap, const float* __restrict__ bias,
             float* __restrict__ outp, int wsel) {
    const float* A = (IN_MODE == 0) ? Ap : (const float*)g_att;
    const float* Wt = g_wt[wsel];
    float* out = (OUT_MODE == 2) ? (float*)g_q : outp;

    __shared__ float smA[128][36];
    __shared__ float smB[128][36];
    __shared__ float smBias[128];

    const int tid = threadIdx.x;
    const int lane = tid & 31;
    const int wid = tid >> 5;
    const int warp_m = wid >> 2;
    const int warp_n = wid & 3;
    const int g = lane >> 2;
    const int c = lane & 3;
    const int m0 = blockIdx.y * 128;
    const int n0 = blockIdx.x * 128;

    if (tid < 128) smBias[tid] = bias[n0 + tid];

    float acc[4][4][4];
#pragma unroll
    for (int mt = 0; mt < 4; mt++)
#pragma unroll
        for (int nt = 0; nt < 4; nt++)
#pragma unroll
            for (int i = 0; i < 4; i++) acc[mt][nt][i] = 0.0f;

    for (int kt = 0; kt < 32; kt++) {
        float4 aq[4], bq[4];
#pragma unroll
        for (int it = 0; it < 4; it++) {
            int idx = tid + it * 256;
            int r = idx >> 3;
            int k4 = (idx & 7) * 4;
            aq[it] = *(const float4*)(A + (size_t)(m0 + r) * CDIM + kt * 32 + k4);
            bq[it] = *(const float4*)(Wt + (size_t)(n0 + r) * CDIM + kt * 32 + k4);
        }
        __syncthreads();
#pragma unroll
        for (int it = 0; it < 4; it++) {
            int idx = tid + it * 256;
            int r = idx >> 3;
            int k4 = (idx & 7) * 4;
            int base = (k4 & ~7) + ((k4 & 4) ? 1 : 0);
            float av[4] = {aq[it].x, aq[it].y, aq[it].z, aq[it].w};
            float bv[4] = {bq[it].x, bq[it].y, bq[it].z, bq[it].w};
#pragma unroll
            for (int i = 0; i < 4; i++) {
                smA[r][base + i * 2] = to_tf32(av[i]);
                smB[r][base + i * 2] = bv[i];
            }
        }
        __syncthreads();

#pragma unroll
        for (int ks = 0; ks < 4; ks++) {
            float afr[4][4];
#pragma unroll
            for (int mt = 0; mt < 4; mt++) {
                int r0 = warp_m * 64 + mt * 16 + g;
                float2 A0 = *(float2*)&smA[r0][ks * 8 + 2 * c];
                float2 A1 = *(float2*)&smA[r0 + 8][ks * 8 + 2 * c];
                afr[mt][0] = A0.x; afr[mt][1] = A1.x;
                afr[mt][2] = A0.y; afr[mt][3] = A1.y;
            }
            float bfr[4][2];
#pragma unroll
            for (int nt = 0; nt < 4; nt++) {
                int n = warp_n * 32 + nt * 8 + g;
                float2 B0 = *(float2*)&smB[n][ks * 8 + 2 * c];
                bfr[nt][0] = B0.x; bfr[nt][1] = B0.y;
            }
#pragma unroll
            for (int mt = 0; mt < 4; mt++)
#pragma unroll
                for (int nt = 0; nt < 4; nt++)
                    mma_tf32(acc[mt][nt], afr[mt], bfr[nt]);
        }
    }

#pragma unroll
    for (int mt = 0; mt < 4; mt++) {
        const int row0 = m0 + warp_m * 64 + mt * 16 + g;
#pragma unroll
        for (int nt = 0; nt < 4; nt++) {
            const int cl = warp_n * 32 + nt * 8 + 2 * c;
            const int nb = n0 + cl;
            float2 v0 = make_float2(acc[mt][nt][0] + smBias[cl],
                                    acc[mt][nt][1] + smBias[cl + 1]);
            float2 v1 = make_float2(acc[mt][nt][2] + smBias[cl],
                                    acc[mt][nt][3] + smBias[cl + 1]);
            if (OUT_MODE == 0) {
                *(float2*)(out + (size_t)row0 * CDIM + nb) = v0;
                *(float2*)(out + (size_t)(row0 + 8) * CDIM + nb) = v1;
            } else {
                const int h = nb >> 6, d0 = nb & 63;
                const int b0 = row0 >> 11, t0 = row0 & 2047;
                const int b1 = (row0 + 8) >> 11, t1 = (row0 + 8) & 2047;
                *(float2*)(out + (((size_t)(b0 * HN + h) * TSEQ + t0) * DH + d0)) = v0;
                *(float2*)(out + (((size_t)(b1 * HN + h) * TSEQ + t1) * DH + d0)) = v1;
            }
        }
    }
}

// ---------------------------------------------------------------------------
// Tensor-core causal flash attention (tf32 mma.sync).
// Grid (T/128, B*H), 256 threads = 8 warps; warp w owns rows [w*16, w*16+16).
// Ks/Vts stored with the k-permuted layout (src col k -> pos (k%4)*2 + k/4)
// so a float2 at 2c yields the B-fragment {k=c, k=c+4}.
// ---------------------------------------------------------------------------
__global__ __launch_bounds__(256, 2) void attn_tc(const float* __restrict__ kglob) {
    const float* qg = (const float*)g_q;
    const float* vtg = (const float*)g_vt;
    float* yo = (float*)g_att;

    __shared__ float Ks[32][68];       // [key][d-permuted]
    __shared__ float Vts[64][36];      // [d][key-permuted]
    __shared__ float Ps[8][16][36];    // per-warp P staging (natural key order)

    const int tid = threadIdx.x;
    const int lane = tid & 31;
    const int w = tid >> 5;
    const int g = lane >> 2;
    const int c = lane & 3;

    const int iq = gridDim.x - 1 - blockIdx.x;   // heavy tiles first
    const int bh = blockIdx.y;
    const int row0 = iq * 128 + w * 16;
    const int rg = row0 + g;
    const int rg8 = rg + 8;

    const float* qb = qg + (size_t)bh * TSEQ * DH;
    const float* kb = kglob + (size_t)bh * TSEQ * DH;
    const float* vtb = vtg + (size_t)bh * DH * TSEQ;

    // Q fragments in registers (1/sqrt(D) folded, tf32-rounded)
    float qf[8][4];
#pragma unroll
    for (int kk = 0; kk < 8; kk++) {
        qf[kk][0] = to_tf32(qb[(size_t)rg * DH + kk * 8 + c] * 0.125f);
        qf[kk][1] = to_tf32(qb[(size_t)rg8 * DH + kk * 8 + c] * 0.125f);
        qf[kk][2] = to_tf32(qb[(size_t)rg * DH + kk * 8 + c + 4] * 0.125f);
        qf[kk][3] = to_tf32(qb[(size_t)rg8 * DH + kk * 8 + c + 4] * 0.125f);
    }

    float o[8][4];
#pragma unroll
    for (int nt = 0; nt < 8; nt++)
#pragma unroll
        for (int i = 0; i < 4; i++) o[nt][i] = 0.0f;
    float m0 = -1e30f, m1 = -1e30f, l0 = 0.0f, l1 = 0.0f;

    const int ntiles = 4 * iq + 4;
    for (int j = 0; j < ntiles; j++) {
        __syncthreads();   // all warps done with Ks/Vts of prev tile
#pragma unroll
        for (int it = 0; it < 2; it++) {
            int idx = tid + it * 256;
            // K tile: rows 0..31, d 0..63 (permuted within 8-groups, rounded)
            int r = idx >> 4, c4 = (idx & 15) * 4;
            float4 a = *(const float4*)(kb + (size_t)(j * 32 + r) * DH + c4);
            int kbase = (c4 & ~7) + ((c4 & 4) ? 1 : 0);
            Ks[r][kbase + 0] = to_tf32(a.x);
            Ks[r][kbase + 2] = to_tf32(a.y);
            Ks[r][kbase + 4] = to_tf32(a.z);
            Ks[r][kbase + 6] = to_tf32(a.w);
            // V^T tile: d 0..63, keys 0..31 (permuted; pre-rounded in transpose_v)
            int d = idx >> 3, k4 = (idx & 7) * 4;
            float4 b = *(const float4*)(vtb + (size_t)d * TSEQ + j * 32 + k4);
            int vbase = (k4 & ~7) + ((k4 & 4) ? 1 : 0);
            Vts[d][vbase + 0] = b.x;
            Vts[d][vbase + 2] = b.y;
            Vts[d][vbase + 4] = b.z;
            Vts[d][vbase + 6] = b.w;
        }
        __syncthreads();
        if (j * 32 > row0 + 15) continue;   // warp fully masked for this tile

        // S = Q K^T  (16 x 32)
        float s[4][4];
#pragma unroll
        for (int nt = 0; nt < 4; nt++)
#pragma unroll
            for (int i = 0; i < 4; i++) s[nt][i] = 0.0f;
#pragma unroll
        for (int kk = 0; kk < 8; kk++) {
#pragma unroll
            for (int nt = 0; nt < 4; nt++) {
                float2 bfr = *(float2*)&Ks[nt * 8 + g][kk * 8 + 2 * c];
                mma_tf32(s[nt], qf[kk], (const float*)&bfr);
            }
        }

        // causal mask (only possible on the last 4 tiles)
        if (j >= 4 * iq) {
#pragma unroll
            for (int nt = 0; nt < 4; nt++) {
                int kg = j * 32 + nt * 8 + 2 * c;
                if (kg > rg)      s[nt][0] = -1e30f;
                if (kg + 1 > rg)  s[nt][1] = -1e30f;
                if (kg > rg8)     s[nt][2] = -1e30f;
                if (kg + 1 > rg8) s[nt][3] = -1e30f;
            }
        }

        // row max over regs + 4 c-lanes
        float t0 = fmaxf(s[0][0], s[0][1]);
        float t1 = fmaxf(s[0][2], s[0][3]);
#pragma unroll
        for (int nt = 1; nt < 4; nt++) {
            t0 = fmaxf(t0, fmaxf(s[nt][0], s[nt][1]));
            t1 = fmaxf(t1, fmaxf(s[nt][2], s[nt][3]));
        }
        t0 = fmaxf(t0, __shfl_xor_sync(0xffffffffu, t0, 1));
        t0 = fmaxf(t0, __shfl_xor_sync(0xffffffffu, t0, 2));
        t1 = fmaxf(t1, __shfl_xor_sync(0xffffffffu, t1, 1));
        t1 = fmaxf(t1, __shfl_xor_sync(0xffffffffu, t1, 2));

        float mn0 = fmaxf(m0, t0), mn1 = fmaxf(m1, t1);
        float a0 = __expf(m0 - mn0), a1 = __expf(m1 - mn1);
        m0 = mn0; m1 = mn1;

        float rs0 = 0.0f, rs1 = 0.0f;
#pragma unroll
        for (int nt = 0; nt < 4; nt++) {
            s[nt][0] = __expf(s[nt][0] - m0);
            s[nt][1] = __expf(s[nt][1] - m0);
            s[nt][2] = __expf(s[nt][2] - m1);
            s[nt][3] = __expf(s[nt][3] - m1);
            rs0 += s[nt][0] + s[nt][1];
            rs1 += s[nt][2] + s[nt][3];
        }
        rs0 += __shfl_xor_sync(0xffffffffu, rs0, 1);
        rs0 += __shfl_xor_sync(0xffffffffu, rs0, 2);
        rs1 += __shfl_xor_sync(0xffffffffu, rs1, 1);
        rs1 += __shfl_xor_sync(0xffffffffu, rs1, 2);
        l0 = l0 * a0 + rs0;
        l1 = l1 * a1 + rs1;

#pragma unroll
        for (int nt = 0; nt < 8; nt++) {
            o[nt][0] *= a0; o[nt][1] *= a0;
            o[nt][2] *= a1; o[nt][3] *= a1;
        }

        // P: C-layout -> A-layout via warp-private smem (tf32-rounded)
#pragma unroll
        for (int nt = 0; nt < 4; nt++) {
            *(float2*)&Ps[w][g][nt * 8 + 2 * c] =
                make_float2(to_tf32(s[nt][0]), to_tf32(s[nt][1]));
            *(float2*)&Ps[w][g + 8][nt * 8 + 2 * c] =
                make_float2(to_tf32(s[nt][2]), to_tf32(s[nt][3]));
        }
        __syncwarp();

        // O += P V
#pragma unroll
        for (int kk = 0; kk < 4; kk++) {
            float af[4];
            af[0] = Ps[w][g][kk * 8 + c];
            af[1] = Ps[w][g + 8][kk * 8 + c];
            af[2] = Ps[w][g][kk * 8 + c + 4];
            af[3] = Ps[w][g + 8][kk * 8 + c + 4];
#pragma unroll
            for (int nt = 0; nt < 8; nt++) {
                float2 bfr = *(float2*)&Vts[nt * 8 + g][kk * 8 + 2 * c];
                mma_tf32(o[nt], af, (const float*)&bfr);
            }
        }
        __syncwarp();   // Ps reads done before next tile overwrites
    }

    // normalize + write to (B,T,C)
    const int b = bh >> 4, h = bh & 15;
    const float i0 = 1.0f / l0, i1 = 1.0f / l1;
    float* y0 = yo + ((size_t)(b * TSEQ + rg) * CDIM + h * 64);
    float* y1 = yo + ((size_t)(b * TSEQ + rg8) * CDIM + h * 64);
#pragma unroll
    for (int nt = 0; nt < 8; nt++) {
        int d = nt * 8 + 2 * c;
        *(float2*)(y0 + d) = make_float2(o[nt][0] * i0, o[nt][1] * i0);
        *(float2*)(y1 + d) = make_float2(o[nt][2] * i1, o[nt][3] * i1);
    }
}

// ---------------------------------------------------------------------------
extern "C" void kernel_launch(void* const* d_in, const int* in_sizes, int n_in,
                              void* d_out, int out_size) {
    const float* x  = (const float*)d_in[0];
    const float* wq = (const float*)d_in[1];
    const float* bq = (const float*)d_in[2];
    const float* wk = (const float*)d_in[3];
    const float* bk = (const float*)d_in[4];
    const float* wv = (const float*)d_in[5];
    const float* bv = (const float*)d_in[6];
    const float* wp = (const float*)d_in[7];
    const float* bp = (const float*)d_in[8];

    float* out  = (float*)d_out;
    float* kout = out + (size_t)BSZ * TSEQ * CDIM;       // present[0] (k)
    float* vout = kout + (size_t)BSZ * HN * TSEQ * DH;   // present[1] (v)

    transpose_w<<<dim3(32, 32, 4), dim3(32, 8)>>>(wq, wk, wv, wp);

    dim3 gg(8, 64);   // N/128, M/128
    gemm_tc<0, 2><<<gg, 256>>>(x, bq, nullptr, 0);   // q -> g_q
    gemm_tc<0, 1><<<gg, 256>>>(x, bk, kout, 1);      // k -> present[0]
    gemm_tc<0, 1><<<gg, 256>>>(x, bv, vout, 2);      // v -> present[1]

    transpose_v<<<dim3(TSEQ / 32, DH / 32, BSZ * HN), dim3(32, 8)>>>(vout);

    attn_tc<<<dim3(TSEQ / 128, BSZ * HN), 256>>>(kout);

    gemm_tc<1, 0><<<gg, 256>>>(nullptr, bp, out, 3); // y = att @ wp + bp
}

// round 12
// speedup vs baseline: 2.7191x; 1.1060x over previous
#include <cuda_runtime.h>
#include <stdint.h>
#include <math.h>

#define BSZ 4
#define TSEQ 2048
#define CDIM 1024
#define HN 16
#define DH 64

// __device__ scratch (allocation-free rule)
__device__ float g_q[(size_t)BSZ * HN * TSEQ * DH];    // (B,H,T,D)
__device__ float g_att[(size_t)BSZ * TSEQ * CDIM];     // (B,T,C)
__device__ float g_wt[4][(size_t)CDIM * CDIM];         // transposed+rounded weights [n][k]
__device__ float g_vt[(size_t)BSZ * HN * DH * TSEQ];   // V transposed (B,H,D,T), tf32-rounded

__device__ __forceinline__ float to_tf32(float x) {
    float r; asm("cvt.rna.tf32.f32 %0, %1;" : "=f"(r) : "f"(x)); return r;
}

__device__ __forceinline__ void mma_tf32(float* d, const float* a, const float* b) {
    asm("mma.sync.aligned.m16n8k8.row.col.f32.tf32.tf32.f32 "
        "{%0,%1,%2,%3}, {%4,%5,%6,%7}, {%8,%9}, {%0,%1,%2,%3};"
        : "+f"(d[0]), "+f"(d[1]), "+f"(d[2]), "+f"(d[3])
        : "f"(a[0]), "f"(a[1]), "f"(a[2]), "f"(a[3]), "f"(b[0]), "f"(b[1]));
}

// ---------------------------------------------------------------------------
// weight transpose + tf32 rounding: g_wt[z][n][k] = rna(w_z[k][n])
// ---------------------------------------------------------------------------
__global__ void transpose_w(const float* __restrict__ w0, const float* __restrict__ w1,
                            const float* __restrict__ w2, const float* __restrict__ w3) {
    __shared__ float t[32][33];
    const float* src = (blockIdx.z == 0) ? w0 : (blockIdx.z == 1) ? w1
                     : (blockIdx.z == 2) ? w2 : w3;
    float* dst = g_wt[blockIdx.z];
    const int n0 = blockIdx.x * 32, k0 = blockIdx.y * 32;
    const int x = threadIdx.x, y = threadIdx.y;
#pragma unroll
    for (int i = 0; i < 32; i += 8)
        t[y + i][x] = src[(size_t)(k0 + y + i) * CDIM + n0 + x];
    __syncthreads();
#pragma unroll
    for (int i = 0; i < 32; i += 8)
        dst[(size_t)(n0 + y + i) * CDIM + k0 + x] = to_tf32(t[x][y + i]);
}

// ---------------------------------------------------------------------------
// V transpose + tf32 rounding: g_vt[bh][d][t] = rna(vout[bh][t][d])
// ---------------------------------------------------------------------------
__global__ void transpose_v(const float* __restrict__ v) {
    __shared__ float t[32][33];
    const int bh = blockIdx.z;
    const int t0 = blockIdx.x * 32, d0 = blockIdx.y * 32;
    const int x = threadIdx.x, y = threadIdx.y;
    const float* src = v + (size_t)bh * TSEQ * DH;
    float* dst = (float*)g_vt + (size_t)bh * DH * TSEQ;
#pragma unroll
    for (int i = 0; i < 32; i += 8)
        t[y + i][x] = src[(size_t)(t0 + y + i) * DH + d0 + x];
    __syncthreads();
#pragma unroll
    for (int i = 0; i < 32; i += 8)
        dst[(size_t)(d0 + y + i) * TSEQ + t0 + x] = to_tf32(t[x][y + i]);
}

// ---------------------------------------------------------------------------
// tf32 mma.sync GEMM: out = A @ W + bias
// Block 128x128, BK=32, 128 threads (4 warps, 2x2 grid, warp = 64x64).
// Per ks-step: 16 LDS.64 -> 32 mma. Smem k-permuted (k -> (k%4)*2 + k/4),
// written as 2 STS.128 per 8-group: {k0,k4,k1,k5} {k2,k6,k3,k7}.
// ---------------------------------------------------------------------------
template <int IN_MODE, int OUT_MODE>
__global__ __launch_bounds__(128, 2)
void gemm_tc(const float* __restrict__ Ap, const float* __restrict__ bias,
             float* __restrict__ outp, int wsel) {
    const float* A = (IN_MODE == 0) ? Ap : (const float*)g_att;
    const float* Wt = g_wt[wsel];
    float* out = (OUT_MODE == 2) ? (float*)g_q : outp;

    __shared__ float smA[128][36];
    __shared__ float smB[128][36];
    __shared__ float smBias[128];

    const int tid = threadIdx.x;
    const int lane = tid & 31;
    const int wid = tid >> 5;
    const int warp_m = wid >> 1;     // 0..1 (x64 rows)
    const int warp_n = wid & 1;      // 0..1 (x64 cols)
    const int g = lane >> 2;         // 0..7
    const int c = lane & 3;          // 0..3
    const int m0 = blockIdx.y * 128;
    const int n0 = blockIdx.x * 128;

    smBias[tid] = bias[n0 + tid];

    float acc[4][8][4];
#pragma unroll
    for (int mt = 0; mt < 4; mt++)
#pragma unroll
        for (int nt = 0; nt < 8; nt++)
#pragma unroll
            for (int i = 0; i < 4; i++) acc[mt][nt][i] = 0.0f;

    for (int kt = 0; kt < 32; kt++) {
        // prefetch: each thread owns 4 8-groups per operand (512 groups total)
        float4 a0[4], a1[4], b0[4], b1[4];
#pragma unroll
        for (int it = 0; it < 4; it++) {
            int grp = tid + it * 128;         // 0..511
            int r = grp >> 2;                 // 0..127
            int gk = (grp & 3) * 8;           // 0,8,16,24
            const float* ap = A + (size_t)(m0 + r) * CDIM + kt * 32 + gk;
            const float* bp = Wt + (size_t)(n0 + r) * CDIM + kt * 32 + gk;
            a0[it] = *(const float4*)ap;
            a1[it] = *(const float4*)(ap + 4);
            b0[it] = *(const float4*)bp;
            b1[it] = *(const float4*)(bp + 4);
        }
        __syncthreads();   // previous compute done reading smem
#pragma unroll
        for (int it = 0; it < 4; it++) {
            int grp = tid + it * 128;
            int r = grp >> 2;
            int gk = (grp & 3) * 8;
            // permuted-pair layout: pos 2j -> k=j, pos 2j+1 -> k=j+4
            *(float4*)&smA[r][gk] = make_float4(to_tf32(a0[it].x), to_tf32(a1[it].x),
                                                to_tf32(a0[it].y), to_tf32(a1[it].y));
            *(float4*)&smA[r][gk + 4] = make_float4(to_tf32(a0[it].z), to_tf32(a1[it].z),
                                                    to_tf32(a0[it].w), to_tf32(a1[it].w));
            *(float4*)&smB[r][gk] = make_float4(b0[it].x, b1[it].x, b0[it].y, b1[it].y);
            *(float4*)&smB[r][gk + 4] = make_float4(b0[it].z, b1[it].z, b0[it].w, b1[it].w);
        }
        __syncthreads();

#pragma unroll
        for (int ks = 0; ks < 4; ks++) {
            float afr[4][4];
#pragma unroll
            for (int mt = 0; mt < 4; mt++) {
                int r0 = warp_m * 64 + mt * 16 + g;
                float2 A0 = *(float2*)&smA[r0][ks * 8 + 2 * c];
                float2 A1 = *(float2*)&smA[r0 + 8][ks * 8 + 2 * c];
                afr[mt][0] = A0.x; afr[mt][1] = A1.x;
                afr[mt][2] = A0.y; afr[mt][3] = A1.y;
            }
            float bfr[8][2];
#pragma unroll
            for (int nt = 0; nt < 8; nt++) {
                int n = warp_n * 64 + nt * 8 + g;
                float2 B0 = *(float2*)&smB[n][ks * 8 + 2 * c];
                bfr[nt][0] = B0.x; bfr[nt][1] = B0.y;
            }
#pragma unroll
            for (int mt = 0; mt < 4; mt++)
#pragma unroll
                for (int nt = 0; nt < 8; nt++)
                    mma_tf32(acc[mt][nt], afr[mt], bfr[nt]);
        }
    }

#pragma unroll
    for (int mt = 0; mt < 4; mt++) {
        const int row0 = m0 + warp_m * 64 + mt * 16 + g;
#pragma unroll
        for (int nt = 0; nt < 8; nt++) {
            const int cl = warp_n * 64 + nt * 8 + 2 * c;
            const int nb = n0 + cl;
            float2 v0 = make_float2(acc[mt][nt][0] + smBias[cl],
                                    acc[mt][nt][1] + smBias[cl + 1]);
            float2 v1 = make_float2(acc[mt][nt][2] + smBias[cl],
                                    acc[mt][nt][3] + smBias[cl + 1]);
            if (OUT_MODE == 0) {
                *(float2*)(out + (size_t)row0 * CDIM + nb) = v0;
                *(float2*)(out + (size_t)(row0 + 8) * CDIM + nb) = v1;
            } else {
                const int h = nb >> 6, d0 = nb & 63;
                const int b0 = row0 >> 11, t0 = row0 & 2047;
                const int b1 = (row0 + 8) >> 11, t1 = (row0 + 8) & 2047;
                *(float2*)(out + (((size_t)(b0 * HN + h) * TSEQ + t0) * DH + d0)) = v0;
                *(float2*)(out + (((size_t)(b1 * HN + h) * TSEQ + t1) * DH + d0)) = v1;
            }
        }
    }
}

// ---------------------------------------------------------------------------
// Tensor-core causal flash attention (tf32 mma.sync) — unchanged from R7.
// ---------------------------------------------------------------------------
__global__ __launch_bounds__(256, 2) void attn_tc(const float* __restrict__ kglob) {
    const float* qg = (const float*)g_q;
    const float* vtg = (const float*)g_vt;
    float* yo = (float*)g_att;

    __shared__ float Ks[32][68];       // [key][d-permuted]
    __shared__ float Vts[64][36];      // [d][key-permuted]
    __shared__ float Ps[8][16][36];    // per-warp P staging

    const int tid = threadIdx.x;
    const int lane = tid & 31;
    const int w = tid >> 5;
    const int g = lane >> 2;
    const int c = lane & 3;

    const int iq = gridDim.x - 1 - blockIdx.x;
    const int bh = blockIdx.y;
    const int row0 = iq * 128 + w * 16;
    const int rg = row0 + g;
    const int rg8 = rg + 8;

    const float* qb = qg + (size_t)bh * TSEQ * DH;
    const float* kb = kglob + (size_t)bh * TSEQ * DH;
    const float* vtb = vtg + (size_t)bh * DH * TSEQ;

    float qf[8][4];
#pragma unroll
    for (int kk = 0; kk < 8; kk++) {
        qf[kk][0] = to_tf32(qb[(size_t)rg * DH + kk * 8 + c] * 0.125f);
        qf[kk][1] = to_tf32(qb[(size_t)rg8 * DH + kk * 8 + c] * 0.125f);
        qf[kk][2] = to_tf32(qb[(size_t)rg * DH + kk * 8 + c + 4] * 0.125f);
        qf[kk][3] = to_tf32(qb[(size_t)rg8 * DH + kk * 8 + c + 4] * 0.125f);
    }

    float o[8][4];
#pragma unroll
    for (int nt = 0; nt < 8; nt++)
#pragma unroll
        for (int i = 0; i < 4; i++) o[nt][i] = 0.0f;
    float m0 = -1e30f, m1 = -1e30f, l0 = 0.0f, l1 = 0.0f;

    const int ntiles = 4 * iq + 4;
    for (int j = 0; j < ntiles; j++) {
        __syncthreads();
#pragma unroll
        for (int it = 0; it < 2; it++) {
            int idx = tid + it * 256;
            int r = idx >> 4, c4 = (idx & 15) * 4;
            float4 a = *(const float4*)(kb + (size_t)(j * 32 + r) * DH + c4);
            int kbase = (c4 & ~7) + ((c4 & 4) ? 1 : 0);
            Ks[r][kbase + 0] = to_tf32(a.x);
            Ks[r][kbase + 2] = to_tf32(a.y);
            Ks[r][kbase + 4] = to_tf32(a.z);
            Ks[r][kbase + 6] = to_tf32(a.w);
            int d = idx >> 3, k4 = (idx & 7) * 4;
            float4 b = *(const float4*)(vtb + (size_t)d * TSEQ + j * 32 + k4);
            int vbase = (k4 & ~7) + ((k4 & 4) ? 1 : 0);
            Vts[d][vbase + 0] = b.x;
            Vts[d][vbase + 2] = b.y;
            Vts[d][vbase + 4] = b.z;
            Vts[d][vbase + 6] = b.w;
        }
        __syncthreads();
        if (j * 32 > row0 + 15) continue;

        float s[4][4];
#pragma unroll
        for (int nt = 0; nt < 4; nt++)
#pragma unroll
            for (int i = 0; i < 4; i++) s[nt][i] = 0.0f;
#pragma unroll
        for (int kk = 0; kk < 8; kk++) {
#pragma unroll
            for (int nt = 0; nt < 4; nt++) {
                float2 bfr = *(float2*)&Ks[nt * 8 + g][kk * 8 + 2 * c];
                mma_tf32(s[nt], qf[kk], (const float*)&bfr);
            }
        }

        if (j >= 4 * iq) {
#pragma unroll
            for (int nt = 0; nt < 4; nt++) {
                int kg = j * 32 + nt * 8 + 2 * c;
                if (kg > rg)      s[nt][0] = -1e30f;
                if (kg + 1 > rg)  s[nt][1] = -1e30f;
                if (kg > rg8)     s[nt][2] = -1e30f;
                if (kg + 1 > rg8) s[nt][3] = -1e30f;
            }
        }

        float t0 = fmaxf(s[0][0], s[0][1]);
        float t1 = fmaxf(s[0][2], s[0][3]);
#pragma unroll
        for (int nt = 1; nt < 4; nt++) {
            t0 = fmaxf(t0, fmaxf(s[nt][0], s[nt][1]));
            t1 = fmaxf(t1, fmaxf(s[nt][2], s[nt][3]));
        }
        t0 = fmaxf(t0, __shfl_xor_sync(0xffffffffu, t0, 1));
        t0 = fmaxf(t0, __shfl_xor_sync(0xffffffffu, t0, 2));
        t1 = fmaxf(t1, __shfl_xor_sync(0xffffffffu, t1, 1));
        t1 = fmaxf(t1, __shfl_xor_sync(0xffffffffu, t1, 2));

        float mn0 = fmaxf(m0, t0), mn1 = fmaxf(m1, t1);
        float a0 = __expf(m0 - mn0), a1 = __expf(m1 - mn1);
        m0 = mn0; m1 = mn1;

        float rs0 = 0.0f, rs1 = 0.0f;
#pragma unroll
        for (int nt = 0; nt < 4; nt++) {
            s[nt][0] = __expf(s[nt][0] - m0);
            s[nt][1] = __expf(s[nt][1] - m0);
            s[nt][2] = __expf(s[nt][2] - m1);
            s[nt][3] = __expf(s[nt][3] - m1);
            rs0 += s[nt][0] + s[nt][1];
            rs1 += s[nt][2] + s[nt][3];
        }
        rs0 += __shfl_xor_sync(0xffffffffu, rs0, 1);
        rs0 += __shfl_xor_sync(0xffffffffu, rs0, 2);
        rs1 += __shfl_xor_sync(0xffffffffu, rs1, 1);
        rs1 += __shfl_xor_sync(0xffffffffu, rs1, 2);
        l0 = l0 * a0 + rs0;
        l1 = l1 * a1 + rs1;

#pragma unroll
        for (int nt = 0; nt < 8; nt++) {
            o[nt][0] *= a0; o[nt][1] *= a0;
            o[nt][2] *= a1; o[nt][3] *= a1;
        }

#pragma unroll
        for (int nt = 0; nt < 4; nt++) {
            *(float2*)&Ps[w][g][nt * 8 + 2 * c] =
                make_float2(to_tf32(s[nt][0]), to_tf32(s[nt][1]));
            *(float2*)&Ps[w][g + 8][nt * 8 + 2 * c] =
                make_float2(to_tf32(s[nt][2]), to_tf32(s[nt][3]));
        }
        __syncwarp();

#pragma unroll
        for (int kk = 0; kk < 4; kk++) {
            float af[4];
            af[0] = Ps[w][g][kk * 8 + c];
            af[1] = Ps[w][g + 8][kk * 8 + c];
            af[2] = Ps[w][g][kk * 8 + c + 4];
            af[3] = Ps[w][g + 8][kk * 8 + c + 4];
#pragma unroll
            for (int nt = 0; nt < 8; nt++) {
                float2 bfr = *(float2*)&Vts[nt * 8 + g][kk * 8 + 2 * c];
                mma_tf32(o[nt], af, (const float*)&bfr);
            }
        }
        __syncwarp();
    }

    const int b = bh >> 4, h = bh & 15;
    const float i0 = 1.0f / l0, i1 = 1.0f / l1;
    float* y0 = yo + ((size_t)(b * TSEQ + rg) * CDIM + h * 64);
    float* y1 = yo + ((size_t)(b * TSEQ + rg8) * CDIM + h * 64);
#pragma unroll
    for (int nt = 0; nt < 8; nt++) {
        int d = nt * 8 + 2 * c;
        *(float2*)(y0 + d) = make_float2(o[nt][0] * i0, o[nt][1] * i0);
        *(float2*)(y1 + d) = make_float2(o[nt][2] * i1, o[nt][3] * i1);
    }
}

// ---------------------------------------------------------------------------
extern "C" void kernel_launch(void* const* d_in, const int* in_sizes, int n_in,
                              void* d_out, int out_size) {
    const float* x  = (const float*)d_in[0];
    const float* wq = (const float*)d_in[1];
    const float* bq = (const float*)d_in[2];
    const float* wk = (const float*)d_in[3];
    const float* bk = (const float*)d_in[4];
    const float* wv = (const float*)d_in[5];
    const float* bv = (const float*)d_in[6];
    const float* wp = (const float*)d_in[7];
    const float* bp = (const float*)d_in[8];

    float* out  = (float*)d_out;
    float* kout = out + (size_t)BSZ * TSEQ * CDIM;       // present[0] (k)
    float* vout = kout + (size_t)BSZ * HN * TSEQ * DH;   // present[1] (v)

    transpose_w<<<dim3(32, 32, 4), dim3(32, 8)>>>(wq, wk, wv, wp);

    dim3 gg(8, 64);   // N/128, M/128
    gemm_tc<0, 2><<<gg, 128>>>(x, bq, nullptr, 0);   // q -> g_q
    gemm_tc<0, 1><<<gg, 128>>>(x, bk, kout, 1);      // k -> present[0]
    gemm_tc<0, 1><<<gg, 128>>>(x, bv, vout, 2);      // v -> present[1]

    transpose_v<<<dim3(TSEQ / 32, DH / 32, BSZ * HN), dim3(32, 8)>>>(vout);

    attn_tc<<<dim3(TSEQ / 128, BSZ * HN), 256>>>(kout);

    gemm_tc<1, 0><<<gg, 128>>>(nullptr, bp, out, 3); // y = att @ wp + bp
}